// round 16
// baseline (speedup 1.0000x reference)
#include <cuda_runtime.h>
#include <cuda_fp16.h>
#include <cstdint>
#include <math.h>

// Problem constants (bi_Mlp: x[64,197,768], H=3072)
#define MTOK 12608
#define CDIM 768
#define HDIM 3072

#define BM 128
#define BN 128
#define BK 96               // halves of K per tile (6 kk-chunks)
#define NSTAGE 2
#define NTHREADS 256        // 8 warps, warp tile 32x64 (validated layout)
#define RSTRIDE_B 208       // bytes per smem row (192 data + 16 pad) -> conflict-free
#define TILE_BYTES (128 * RSTRIDE_B)          // 26624
#define STAGE_BYTES (2 * TILE_BYTES)          // 53248 (A + B)
#define SMEM_TOTAL (NSTAGE * STAGE_BYTES)     // 106496 (2 CTAs/SM fit)

// fused-prep block ranges
#define NB_CONV 512          // convert_x blocks (grid-stride)
#define NB_W1   384          // w1: 8 rows/block (3072 rows)
#define NB_W2   384          // w2: 2 rows/block, 4 warps/row (768 rows)
#define NB_PREP (NB_CONV + NB_W1 + NB_W2)

// Scratch (static device globals: allocation-guard safe)
__device__ __half g_xh[(size_t)MTOK * CDIM];   // x in fp16
__device__ __half g_h [(size_t)MTOK * HDIM];   // hidden (fp16, post-GELU)
__device__ __half g_w1h[(size_t)HDIM * CDIM];  // sign(w1) in fp16
__device__ __half g_w2h[(size_t)CDIM * HDIM];  // sign(w2) in fp16
__device__ float  g_alpha1[HDIM];
__device__ float  g_alpha2[CDIM];

// ---------------------------------------------------------------------------
// helpers
// ---------------------------------------------------------------------------
__device__ __forceinline__ uint32_t smem_u32(const void* p) {
    return (uint32_t)__cvta_generic_to_shared(p);
}
__device__ __forceinline__ void cp_async16(uint32_t dst, const void* src, int src_bytes) {
    asm volatile("cp.async.cg.shared.global [%0], [%1], 16, %2;\n"
                 :: "r"(dst), "l"(src), "r"(src_bytes));
}
__device__ __forceinline__ void cp_commit() {
    asm volatile("cp.async.commit_group;\n" ::: "memory");
}
template <int N>
__device__ __forceinline__ void cp_wait() {
    asm volatile("cp.async.wait_group %0;\n" :: "n"(N) : "memory");
}
__device__ __forceinline__ void ldsm_x4(uint32_t& r0, uint32_t& r1, uint32_t& r2,
                                        uint32_t& r3, uint32_t addr) {
    asm volatile("ldmatrix.sync.aligned.m8n8.x4.shared.b16 {%0,%1,%2,%3}, [%4];\n"
                 : "=r"(r0), "=r"(r1), "=r"(r2), "=r"(r3) : "r"(addr));
}
// fp16 MMA, fp32 accumulate: D[16,8] += A[16,16] * B[16,8]
__device__ __forceinline__ void mma_f16(float c[4], const uint32_t a[4], const uint32_t b[2]) {
    asm volatile(
        "mma.sync.aligned.m16n8k16.row.col.f32.f16.f16.f32 "
        "{%0,%1,%2,%3}, {%4,%5,%6,%7}, {%8,%9}, {%0,%1,%2,%3};\n"
        : "+f"(c[0]), "+f"(c[1]), "+f"(c[2]), "+f"(c[3])
        : "r"(a[0]), "r"(a[1]), "r"(a[2]), "r"(a[3]), "r"(b[0]), "r"(b[1]));
}

__device__ __forceinline__ float sgnf(float v) {
    return (v > 0.f) ? 1.f : ((v < 0.f) ? -1.f : 0.f);
}
__device__ __forceinline__ uint32_t pack_sign2(float a, float b) {
    __half2 h = __floats2half2_rn(sgnf(a), sgnf(b));
    return *(uint32_t*)&h;
}

// ---------------------------------------------------------------------------
// fused prep kernel: one launch does x->fp16, binarize(w1), binarize(w2)
// all paths: 8 floats per thread per iteration, 16B stores
// ---------------------------------------------------------------------------
__global__ void prep_kernel(const float* __restrict__ x, __half* __restrict__ xh, int n8,
                            const float* __restrict__ w1, __half* __restrict__ w1s,
                            float* __restrict__ a1,
                            const float* __restrict__ w2, __half* __restrict__ w2s,
                            float* __restrict__ a2) {
    const int b = blockIdx.x;
    const int tid = threadIdx.x;

    if (b < NB_CONV) {
        // ---- convert x (fp32 -> fp16), grid-stride, 8 floats/iter
        int stride = NB_CONV * blockDim.x;
        const float4* x4 = (const float4*)x;
        uint4* xo = (uint4*)xh;
        for (int i = b * blockDim.x + tid; i < n8; i += stride) {
            float4 v0 = x4[2 * i], v1 = x4[2 * i + 1];
            __half2 h0 = __floats2half2_rn(v0.x, v0.y);
            __half2 h1 = __floats2half2_rn(v0.z, v0.w);
            __half2 h2 = __floats2half2_rn(v1.x, v1.y);
            __half2 h3 = __floats2half2_rn(v1.z, v1.w);
            uint4 u;
            u.x = *(uint32_t*)&h0; u.y = *(uint32_t*)&h1;
            u.z = *(uint32_t*)&h2; u.w = *(uint32_t*)&h3;
            xo[i] = u;
        }
    } else if (b < NB_CONV + NB_W1) {
        // ---- binarize w1 [HDIM x CDIM]: warp-per-row, 8 rows/block
        int r = (b - NB_CONV) * 8 + (tid >> 5);
        if (r >= HDIM) return;
        int lane = tid & 31;
        const float4* wr = (const float4*)(w1 + (size_t)r * CDIM);
        uint4* wsr = (uint4*)(w1s + (size_t)r * CDIM);
        const int nv8 = CDIM >> 3;      // 96 chunks of 8 floats
        float s = 0.f;
        for (int i = lane; i < nv8; i += 32) {
            float4 v0 = wr[2 * i], v1 = wr[2 * i + 1];
            s += fabsf(v0.x) + fabsf(v0.y) + fabsf(v0.z) + fabsf(v0.w)
               + fabsf(v1.x) + fabsf(v1.y) + fabsf(v1.z) + fabsf(v1.w);
            uint4 u;
            u.x = pack_sign2(v0.x, v0.y); u.y = pack_sign2(v0.z, v0.w);
            u.z = pack_sign2(v1.x, v1.y); u.w = pack_sign2(v1.z, v1.w);
            wsr[i] = u;
        }
        #pragma unroll
        for (int o = 16; o; o >>= 1) s += __shfl_xor_sync(0xffffffffu, s, o);
        if (lane == 0) a1[r] = s / (float)CDIM;
    } else {
        // ---- binarize w2 [CDIM x HDIM]: 4 warps per row, 2 rows/block
        int sub = b - NB_CONV - NB_W1;       // 0..383
        int warp = tid >> 5;                 // 0..7
        int r = sub * 2 + (warp >> 2);       // 2 rows per block
        if (r >= CDIM) return;
        int wq = warp & 3;                   // quarter-row owner
        int lane = tid & 31;
        const float4* wr = (const float4*)(w2 + (size_t)r * HDIM);
        uint4* wsr = (uint4*)(w2s + (size_t)r * HDIM);
        const int nv8 = HDIM >> 3;           // 384 chunks of 8 floats
        float s = 0.f;
        for (int i = wq * 32 + lane; i < nv8; i += 128) {
            float4 v0 = wr[2 * i], v1 = wr[2 * i + 1];
            s += fabsf(v0.x) + fabsf(v0.y) + fabsf(v0.z) + fabsf(v0.w)
               + fabsf(v1.x) + fabsf(v1.y) + fabsf(v1.z) + fabsf(v1.w);
            uint4 u;
            u.x = pack_sign2(v0.x, v0.y); u.y = pack_sign2(v0.z, v0.w);
            u.z = pack_sign2(v1.x, v1.y); u.w = pack_sign2(v1.z, v1.w);
            wsr[i] = u;
        }
        __shared__ float red[8];
        #pragma unroll
        for (int o = 16; o; o >>= 1) s += __shfl_xor_sync(0xffffffffu, s, o);
        if (lane == 0) red[warp] = s;
        __syncthreads();
        if (wq == 0 && lane == 0) {
            int base = (warp >> 2) * 4;
            float tot = red[base] + red[base + 1] + red[base + 2] + red[base + 3];
            a2[r] = tot / (float)HDIM;
        }
    }
}

// ---------------------------------------------------------------------------
// GEMM: C[m,n] = epi( alpha[n] * sum_k A[m,k]*B[n,k] + bias[n] )
// A: [M,K] row-major fp16, B: [N,K] row-major fp16 (values ±1)
// 8 warps (wm 0-3, wn 0-1), warp tile 32x64, BK=96, 2-stage cp.async pipeline.
// EPI 0: gelu(exact)+clip -> fp16 (feeds GEMM2); EPI 1: affine -> fp32
// ---------------------------------------------------------------------------
template <int EPI>
__global__ void __launch_bounds__(NTHREADS, 2)
gemm_bin(const __half* __restrict__ A, const __half* __restrict__ B,
         const float* __restrict__ alpha, const float* __restrict__ bias,
         void* __restrict__ outp, int M, int N, int K) {
    extern __shared__ __align__(128) char smem[];
    const uint32_t sb = smem_u32(smem);

    const int tid = threadIdx.x;
    const int lane = tid & 31;
    const int warp = tid >> 5;
    const int wm = warp & 3;   // 4 warps along M (4*32 = 128)
    const int wn = warp >> 2;  // 2 warps along N (2*64 = 128)
    const int m0 = blockIdx.y * BM;
    const int n0 = blockIdx.x * BN;
    const int g = lane >> 2, t = lane & 3;

    // ldmatrix per-lane byte offsets (within stage) — validated grouping
    const int lr8 = lane & 7;
    // A x4 groups: (rows+0,k0) (rows+8,k0) (rows+0,k8) (rows+8,k8)
    const uint32_t a_off = (uint32_t)((wm * 32 + lr8 + ((lane >> 3) & 1) * 8) * RSTRIDE_B
                                      + ((lane >> 4) & 1) * 16);
    // B x4 groups: (rows+0,k0) (rows+0,k8) (rows+8,k0) (rows+8,k8)
    const uint32_t b_off = (uint32_t)(TILE_BYTES
                                      + (wn * 64 + lr8 + ((lane >> 4) & 1) * 8) * RSTRIDE_B
                                      + ((lane >> 3) & 1) * 16);

    float acc[2][8][4];
    #pragma unroll
    for (int i = 0; i < 2; ++i)
        #pragma unroll
        for (int j = 0; j < 8; ++j)
            #pragma unroll
            for (int q = 0; q < 4; ++q) acc[i][j][q] = 0.f;

    const int Ktiles = K / BK;

    // loader: thread owns row = tid&127, seg-group sg = tid>>7 (segs 6sg..6sg+5)
    const int row = tid & 127;
    const int sg = tid >> 7;             // 0..1
    const int am = m0 + row;
    const bool pa = am < M;
    const __half* aB = A + (size_t)(pa ? am : 0) * K + sg * 48;
    const __half* bB = B + (size_t)(n0 + row) * K + sg * 48;
    const uint32_t sA = sb + row * RSTRIDE_B + sg * 96;
    const uint32_t sBB = sA + TILE_BYTES;
    const int abytes = pa ? 16 : 0;

    auto load_tile = [&](int kt, int s) {
        const uint32_t so = (uint32_t)s * STAGE_BYTES;
        const size_t kb = (size_t)kt * BK;
        #pragma unroll
        for (int j = 0; j < 6; ++j) {
            cp_async16(sA + so + j * 16, aB + kb + j * 8, abytes);
            cp_async16(sBB + so + j * 16, bB + kb + j * 8, 16);
        }
    };

    // prologue: stage 0
    load_tile(0, 0);
    cp_commit();

    for (int kt = 0; kt < Ktiles; ++kt) {
        cp_wait<0>();          // tile kt resident
        __syncthreads();       // all warps done reading the other stage

        if (kt + 1 < Ktiles) {
            load_tile(kt + 1, (kt + 1) & 1);
            cp_commit();
        }

        const uint32_t stage = sb + (uint32_t)(kt & 1) * STAGE_BYTES;

        #pragma unroll
        for (int kk = 0; kk < 6; ++kk) {          // six K=16 chunks per BK=96
            uint32_t af[2][4];
            uint32_t bf[8][2];
            ldsm_x4(af[0][0], af[0][1], af[0][2], af[0][3],
                    stage + a_off + kk * 32);
            ldsm_x4(af[1][0], af[1][1], af[1][2], af[1][3],
                    stage + a_off + 16 * RSTRIDE_B + kk * 32);
            #pragma unroll
            for (int p = 0; p < 4; ++p)
                ldsm_x4(bf[2 * p][0], bf[2 * p][1], bf[2 * p + 1][0], bf[2 * p + 1][1],
                        stage + b_off + p * (16 * RSTRIDE_B) + kk * 32);
            #pragma unroll
            for (int mi = 0; mi < 2; ++mi)
                #pragma unroll
                for (int ni = 0; ni < 8; ++ni)
                    mma_f16(acc[mi][ni], af[mi], bf[ni]);
        }
    }

    // epilogue (accumulator layout identical to validated versions)
    #pragma unroll
    for (int ni = 0; ni < 8; ++ni) {
        int col = n0 + wn * 64 + ni * 8 + t * 2;
        float al0 = alpha[col], al1 = alpha[col + 1];
        float bi0 = bias[col], bi1 = bias[col + 1];
        #pragma unroll
        for (int mi = 0; mi < 2; ++mi) {
            int rrow = m0 + wm * 32 + mi * 16 + g;
            #pragma unroll
            for (int h = 0; h < 2; ++h) { // h=0: rows g, h=1: rows g+8
                int r = rrow + h * 8;
                if (r < M) {
                    float v0 = al0 * acc[mi][ni][h * 2 + 0] + bi0;
                    float v1 = al1 * acc[mi][ni][h * 2 + 1] + bi1;
                    if (EPI == 0) {
                        v0 = 0.5f * v0 * (1.f + erff(v0 * 0.7071067811865476f));
                        v1 = 0.5f * v1 * (1.f + erff(v1 * 0.7071067811865476f));
                        v0 = fminf(fmaxf(v0, -10.f), 10.f);
                        v1 = fminf(fmaxf(v1, -10.f), 10.f);
                        __half2 hv = __floats2half2_rn(v0, v1);
                        *(__half2*)((__half*)outp + (size_t)r * N + col) = hv;
                    } else {
                        float2 fv = make_float2(v0, v1);
                        *(float2*)((float*)outp + (size_t)r * N + col) = fv;
                    }
                }
            }
        }
    }
}

// ---------------------------------------------------------------------------
extern "C" void kernel_launch(void* const* d_in, const int* in_sizes, int n_in,
                              void* d_out, int out_size) {
    const float* x  = (const float*)d_in[0];
    const float* w1 = (const float*)d_in[1];
    const float* b1 = (const float*)d_in[2];
    const float* w2 = (const float*)d_in[3];
    const float* b2 = (const float*)d_in[4];

    const int M = in_sizes[0] / CDIM;   // 12608
    const int H = in_sizes[2];          // 3072
    const int C = in_sizes[4];          // 768

    __half *xh, *hbuf, *w1h, *w2h;
    float *a1, *a2;
    cudaGetSymbolAddress((void**)&xh,   g_xh);
    cudaGetSymbolAddress((void**)&hbuf, g_h);
    cudaGetSymbolAddress((void**)&w1h,  g_w1h);
    cudaGetSymbolAddress((void**)&w2h,  g_w2h);
    cudaGetSymbolAddress((void**)&a1,   g_alpha1);
    cudaGetSymbolAddress((void**)&a2,   g_alpha2);

    int n8 = (M * C) / 8;
    prep_kernel<<<NB_PREP, 256>>>(x, xh, n8, w1, w1h, a1, w2, w2h, a2);

    cudaFuncSetAttribute((const void*)gemm_bin<0>,
                         cudaFuncAttributeMaxDynamicSharedMemorySize, SMEM_TOTAL);
    cudaFuncSetAttribute((const void*)gemm_bin<1>,
                         cudaFuncAttributeMaxDynamicSharedMemorySize, SMEM_TOTAL);

    dim3 grid1(H / BN, (M + BM - 1) / BM);   // (24, 99)
    gemm_bin<0><<<grid1, NTHREADS, SMEM_TOTAL>>>(xh, w1h, a1, b1, hbuf, M, H, C);

    dim3 grid2(C / BN, (M + BM - 1) / BM);   // (6, 99)
    gemm_bin<1><<<grid2, NTHREADS, SMEM_TOTAL>>>(hbuf, w2h, a2, b2, d_out, M, C, H);
}

// round 17
// speedup vs baseline: 1.6902x; 1.6902x over previous
#include <cuda_runtime.h>
#include <cuda_fp16.h>
#include <cstdint>
#include <math.h>

// Problem constants (bi_Mlp: x[64,197,768], H=3072)
#define MTOK 12608
#define CDIM 768
#define HDIM 3072

#define BM 128
#define BN 128
#define BK 64               // halves of K per tile (4 kk-chunks)
#define NSTAGE 3
#define NTHREADS 256        // 8 warps, warp tile 32x64 (validated R9/R13 layout)
#define RSTRIDE_B 144       // bytes per smem row (128 data + 16 pad) -> conflict-free
#define TILE_BYTES (128 * RSTRIDE_B)          // 18432
#define STAGE_BYTES (2 * TILE_BYTES)          // 36864 (A + B)
#define SMEM_TOTAL (NSTAGE * STAGE_BYTES)     // 110592

// fused-prep block ranges
#define NB_CONV 512          // convert_x blocks (grid-stride)
#define NB_W1   384          // w1: 8 rows/block (3072 rows)
#define NB_W2   384          // w2: 2 rows/block, 4 warps/row (768 rows)
#define NB_PREP (NB_CONV + NB_W1 + NB_W2)

// Scratch (static device globals: allocation-guard safe)
__device__ __half g_xh[(size_t)MTOK * CDIM];   // x in fp16
__device__ __half g_h [(size_t)MTOK * HDIM];   // hidden (fp16, post-GELU)
__device__ __half g_w1h[(size_t)HDIM * CDIM];  // sign(w1) in fp16
__device__ __half g_w2h[(size_t)CDIM * HDIM];  // sign(w2) in fp16
__device__ float  g_alpha1[HDIM];
__device__ float  g_alpha2[CDIM];

// ---------------------------------------------------------------------------
// helpers
// ---------------------------------------------------------------------------
__device__ __forceinline__ uint32_t smem_u32(const void* p) {
    return (uint32_t)__cvta_generic_to_shared(p);
}
__device__ __forceinline__ void cp_async16(uint32_t dst, const void* src, int src_bytes) {
    asm volatile("cp.async.cg.shared.global [%0], [%1], 16, %2;\n"
                 :: "r"(dst), "l"(src), "r"(src_bytes));
}
__device__ __forceinline__ void cp_commit() {
    asm volatile("cp.async.commit_group;\n" ::: "memory");
}
template <int N>
__device__ __forceinline__ void cp_wait() {
    asm volatile("cp.async.wait_group %0;\n" :: "n"(N) : "memory");
}
__device__ __forceinline__ void ldsm_x4(uint32_t& r0, uint32_t& r1, uint32_t& r2,
                                        uint32_t& r3, uint32_t addr) {
    asm volatile("ldmatrix.sync.aligned.m8n8.x4.shared.b16 {%0,%1,%2,%3}, [%4];\n"
                 : "=r"(r0), "=r"(r1), "=r"(r2), "=r"(r3) : "r"(addr));
}
// fp16 MMA, fp32 accumulate: D[16,8] += A[16,16] * B[16,8]
__device__ __forceinline__ void mma_f16(float c[4], const uint32_t a[4], const uint32_t b[2]) {
    asm volatile(
        "mma.sync.aligned.m16n8k16.row.col.f32.f16.f16.f32 "
        "{%0,%1,%2,%3}, {%4,%5,%6,%7}, {%8,%9}, {%0,%1,%2,%3};\n"
        : "+f"(c[0]), "+f"(c[1]), "+f"(c[2]), "+f"(c[3])
        : "r"(a[0]), "r"(a[1]), "r"(a[2]), "r"(a[3]), "r"(b[0]), "r"(b[1]));
}

__device__ __forceinline__ float sgnf(float v) {
    return (v > 0.f) ? 1.f : ((v < 0.f) ? -1.f : 0.f);
}
__device__ __forceinline__ uint32_t pack_sign2(float a, float b) {
    __half2 h = __floats2half2_rn(sgnf(a), sgnf(b));
    return *(uint32_t*)&h;
}

// ---------------------------------------------------------------------------
// fused prep kernel: one launch does x->fp16, binarize(w1), binarize(w2)
// all paths: 8 floats per thread per iteration, 16B stores (R16-validated, 13.6us)
// ---------------------------------------------------------------------------
__global__ void prep_kernel(const float* __restrict__ x, __half* __restrict__ xh, int n8,
                            const float* __restrict__ w1, __half* __restrict__ w1s,
                            float* __restrict__ a1,
                            const float* __restrict__ w2, __half* __restrict__ w2s,
                            float* __restrict__ a2) {
    const int b = blockIdx.x;
    const int tid = threadIdx.x;

    if (b < NB_CONV) {
        // ---- convert x (fp32 -> fp16), grid-stride, 8 floats/iter
        int stride = NB_CONV * blockDim.x;
        const float4* x4 = (const float4*)x;
        uint4* xo = (uint4*)xh;
        for (int i = b * blockDim.x + tid; i < n8; i += stride) {
            float4 v0 = x4[2 * i], v1 = x4[2 * i + 1];
            __half2 h0 = __floats2half2_rn(v0.x, v0.y);
            __half2 h1 = __floats2half2_rn(v0.z, v0.w);
            __half2 h2 = __floats2half2_rn(v1.x, v1.y);
            __half2 h3 = __floats2half2_rn(v1.z, v1.w);
            uint4 u;
            u.x = *(uint32_t*)&h0; u.y = *(uint32_t*)&h1;
            u.z = *(uint32_t*)&h2; u.w = *(uint32_t*)&h3;
            xo[i] = u;
        }
    } else if (b < NB_CONV + NB_W1) {
        // ---- binarize w1 [HDIM x CDIM]: warp-per-row, 8 rows/block
        int r = (b - NB_CONV) * 8 + (tid >> 5);
        if (r >= HDIM) return;
        int lane = tid & 31;
        const float4* wr = (const float4*)(w1 + (size_t)r * CDIM);
        uint4* wsr = (uint4*)(w1s + (size_t)r * CDIM);
        const int nv8 = CDIM >> 3;      // 96 chunks of 8 floats
        float s = 0.f;
        for (int i = lane; i < nv8; i += 32) {
            float4 v0 = wr[2 * i], v1 = wr[2 * i + 1];
            s += fabsf(v0.x) + fabsf(v0.y) + fabsf(v0.z) + fabsf(v0.w)
               + fabsf(v1.x) + fabsf(v1.y) + fabsf(v1.z) + fabsf(v1.w);
            uint4 u;
            u.x = pack_sign2(v0.x, v0.y); u.y = pack_sign2(v0.z, v0.w);
            u.z = pack_sign2(v1.x, v1.y); u.w = pack_sign2(v1.z, v1.w);
            wsr[i] = u;
        }
        #pragma unroll
        for (int o = 16; o; o >>= 1) s += __shfl_xor_sync(0xffffffffu, s, o);
        if (lane == 0) a1[r] = s / (float)CDIM;
    } else {
        // ---- binarize w2 [CDIM x HDIM]: 4 warps per row, 2 rows/block
        int sub = b - NB_CONV - NB_W1;       // 0..383
        int warp = tid >> 5;                 // 0..7
        int r = sub * 2 + (warp >> 2);       // 2 rows per block
        if (r >= CDIM) return;
        int wq = warp & 3;                   // quarter-row owner
        int lane = tid & 31;
        const float4* wr = (const float4*)(w2 + (size_t)r * HDIM);
        uint4* wsr = (uint4*)(w2s + (size_t)r * HDIM);
        const int nv8 = HDIM >> 3;           // 384 chunks of 8 floats
        float s = 0.f;
        for (int i = wq * 32 + lane; i < nv8; i += 128) {
            float4 v0 = wr[2 * i], v1 = wr[2 * i + 1];
            s += fabsf(v0.x) + fabsf(v0.y) + fabsf(v0.z) + fabsf(v0.w)
               + fabsf(v1.x) + fabsf(v1.y) + fabsf(v1.z) + fabsf(v1.w);
            uint4 u;
            u.x = pack_sign2(v0.x, v0.y); u.y = pack_sign2(v0.z, v0.w);
            u.z = pack_sign2(v1.x, v1.y); u.w = pack_sign2(v1.z, v1.w);
            wsr[i] = u;
        }
        __shared__ float red[8];
        #pragma unroll
        for (int o = 16; o; o >>= 1) s += __shfl_xor_sync(0xffffffffu, s, o);
        if (lane == 0) red[warp] = s;
        __syncthreads();
        if (wq == 0 && lane == 0) {
            int base = (warp >> 2) * 4;
            float tot = red[base] + red[base + 1] + red[base + 2] + red[base + 3];
            a2[r] = tot / (float)HDIM;
        }
    }
}

// ---------------------------------------------------------------------------
// GEMM: C[m,n] = epi( alpha[n] * sum_k A[m,k]*B[n,k] + bias[n] )
// A: [M,K] row-major fp16, B: [N,K] row-major fp16 (values ±1)
// 8 warps (wm 0-3, wn 0-1), warp tile 32x64, BK=64, 3-stage cp.async pipeline.
// EPI 0: gelu(exact)+clip -> fp16 (feeds GEMM2); EPI 1: affine -> fp32
// (byte-for-byte the validated R13 GEMM — GEMM1 195.2us)
// ---------------------------------------------------------------------------
template <int EPI>
__global__ void __launch_bounds__(NTHREADS, 2)
gemm_bin(const __half* __restrict__ A, const __half* __restrict__ B,
         const float* __restrict__ alpha, const float* __restrict__ bias,
         void* __restrict__ outp, int M, int N, int K) {
    extern __shared__ __align__(128) char smem[];
    const uint32_t sb = smem_u32(smem);

    const int tid = threadIdx.x;
    const int lane = tid & 31;
    const int warp = tid >> 5;
    const int wm = warp & 3;   // 4 warps along M (4*32 = 128)
    const int wn = warp >> 2;  // 2 warps along N (2*64 = 128)
    const int m0 = blockIdx.y * BM;
    const int n0 = blockIdx.x * BN;
    const int g = lane >> 2, t = lane & 3;

    // ldmatrix per-lane byte offsets (within stage) — validated grouping
    const int lr8 = lane & 7;
    // A x4 groups: (rows+0,k0) (rows+8,k0) (rows+0,k8) (rows+8,k8)
    const uint32_t a_off = (uint32_t)((wm * 32 + lr8 + ((lane >> 3) & 1) * 8) * RSTRIDE_B
                                      + ((lane >> 4) & 1) * 16);
    // B x4 groups: (rows+0,k0) (rows+0,k8) (rows+8,k0) (rows+8,k8)
    const uint32_t b_off = (uint32_t)(TILE_BYTES
                                      + (wn * 64 + lr8 + ((lane >> 4) & 1) * 8) * RSTRIDE_B
                                      + ((lane >> 3) & 1) * 16);

    float acc[2][8][4];
    #pragma unroll
    for (int i = 0; i < 2; ++i)
        #pragma unroll
        for (int j = 0; j < 8; ++j)
            #pragma unroll
            for (int q = 0; q < 4; ++q) acc[i][j][q] = 0.f;

    const int Ktiles = K / BK;

    // hoisted cp.async bases: thread covers rows (tid>>3)+32p, seg tid&7 (16B)
    const int tr = tid >> 3;             // 0..31
    const int seg = tid & 7;             // 0..7
    const __half* aB = A + (size_t)0 + seg * 8;
    const __half* bB = B + (size_t)(n0 + tr) * K + seg * 8;
    const uint32_t sBase = sb + tr * RSTRIDE_B + seg * 16;

    auto load_tile = [&](int kt, int s) {
        const uint32_t so = (uint32_t)s * STAGE_BYTES;
        const size_t kb = (size_t)kt * BK;
        #pragma unroll
        for (int p = 0; p < 4; ++p) {
            int row = tr + 32 * p;
            int am = m0 + row;
            bool pa = am < M;
            cp_async16(sBase + so + p * (32 * RSTRIDE_B),
                       aB + (size_t)(pa ? am : 0) * K + kb, pa ? 16 : 0);
            cp_async16(sBase + so + p * (32 * RSTRIDE_B) + TILE_BYTES,
                       bB + (size_t)(32 * p) * K + kb, 16);
        }
    };

    // prologue: stages 0,1
    #pragma unroll
    for (int s = 0; s < NSTAGE - 1; ++s) {
        load_tile(s, s);
        cp_commit();
    }

    int stageIdx = 0;
    for (int kt = 0; kt < Ktiles; ++kt) {
        cp_wait<NSTAGE - 2>();
        __syncthreads();

        int knext = kt + NSTAGE - 1;
        int snext = stageIdx + (NSTAGE - 1);
        if (snext >= NSTAGE) snext -= NSTAGE;
        if (knext < Ktiles) load_tile(knext, snext);
        cp_commit();

        const uint32_t stage = sb + (uint32_t)stageIdx * STAGE_BYTES;
        if (++stageIdx == NSTAGE) stageIdx = 0;

        #pragma unroll
        for (int kk = 0; kk < 4; ++kk) {          // four K=16 chunks per BK=64
            uint32_t af[2][4];
            uint32_t bf[8][2];
            ldsm_x4(af[0][0], af[0][1], af[0][2], af[0][3],
                    stage + a_off + kk * 32);
            ldsm_x4(af[1][0], af[1][1], af[1][2], af[1][3],
                    stage + a_off + 16 * RSTRIDE_B + kk * 32);
            #pragma unroll
            for (int p = 0; p < 4; ++p)
                ldsm_x4(bf[2 * p][0], bf[2 * p][1], bf[2 * p + 1][0], bf[2 * p + 1][1],
                        stage + b_off + p * (16 * RSTRIDE_B) + kk * 32);
            #pragma unroll
            for (int mi = 0; mi < 2; ++mi)
                #pragma unroll
                for (int ni = 0; ni < 8; ++ni)
                    mma_f16(acc[mi][ni], af[mi], bf[ni]);
        }
    }

    // epilogue (accumulator layout identical to validated versions)
    #pragma unroll
    for (int ni = 0; ni < 8; ++ni) {
        int col = n0 + wn * 64 + ni * 8 + t * 2;
        float al0 = alpha[col], al1 = alpha[col + 1];
        float bi0 = bias[col], bi1 = bias[col + 1];
        #pragma unroll
        for (int mi = 0; mi < 2; ++mi) {
            int row = m0 + wm * 32 + mi * 16 + g;
            #pragma unroll
            for (int h = 0; h < 2; ++h) { // h=0: rows g, h=1: rows g+8
                int r = row + h * 8;
                if (r < M) {
                    float v0 = al0 * acc[mi][ni][h * 2 + 0] + bi0;
                    float v1 = al1 * acc[mi][ni][h * 2 + 1] + bi1;
                    if (EPI == 0) {
                        v0 = 0.5f * v0 * (1.f + erff(v0 * 0.7071067811865476f));
                        v1 = 0.5f * v1 * (1.f + erff(v1 * 0.7071067811865476f));
                        v0 = fminf(fmaxf(v0, -10.f), 10.f);
                        v1 = fminf(fmaxf(v1, -10.f), 10.f);
                        __half2 hv = __floats2half2_rn(v0, v1);
                        *(__half2*)((__half*)outp + (size_t)r * N + col) = hv;
                    } else {
                        float2 fv = make_float2(v0, v1);
                        *(float2*)((float*)outp + (size_t)r * N + col) = fv;
                    }
                }
            }
        }
    }
}

// ---------------------------------------------------------------------------
extern "C" void kernel_launch(void* const* d_in, const int* in_sizes, int n_in,
                              void* d_out, int out_size) {
    const float* x  = (const float*)d_in[0];
    const float* w1 = (const float*)d_in[1];
    const float* b1 = (const float*)d_in[2];
    const float* w2 = (const float*)d_in[3];
    const float* b2 = (const float*)d_in[4];

    const int M = in_sizes[0] / CDIM;   // 12608
    const int H = in_sizes[2];          // 3072
    const int C = in_sizes[4];          // 768

    __half *xh, *hbuf, *w1h, *w2h;
    float *a1, *a2;
    cudaGetSymbolAddress((void**)&xh,   g_xh);
    cudaGetSymbolAddress((void**)&hbuf, g_h);
    cudaGetSymbolAddress((void**)&w1h,  g_w1h);
    cudaGetSymbolAddress((void**)&w2h,  g_w2h);
    cudaGetSymbolAddress((void**)&a1,   g_alpha1);
    cudaGetSymbolAddress((void**)&a2,   g_alpha2);

    int n8 = (M * C) / 8;
    prep_kernel<<<NB_PREP, 256>>>(x, xh, n8, w1, w1h, a1, w2, w2h, a2);

    cudaFuncSetAttribute((const void*)gemm_bin<0>,
                         cudaFuncAttributeMaxDynamicSharedMemorySize, SMEM_TOTAL);
    cudaFuncSetAttribute((const void*)gemm_bin<1>,
                         cudaFuncAttributeMaxDynamicSharedMemorySize, SMEM_TOTAL);

    dim3 grid1(H / BN, (M + BM - 1) / BM);   // (24, 99)
    gemm_bin<0><<<grid1, NTHREADS, SMEM_TOTAL>>>(xh, w1h, a1, b1, hbuf, M, H, C);

    dim3 grid2(C / BN, (M + BM - 1) / BM);   // (6, 99)
    gemm_bin<1><<<grid2, NTHREADS, SMEM_TOTAL>>>(hbuf, w2h, a2, b2, d_out, M, C, H);
}